// round 1
// baseline (speedup 1.0000x reference)
#include <cuda_runtime.h>
#include <cuda_bf16.h>
#include <math.h>

#define S_LEN 2048
#define EMB   2048
#define NHEAD 16
#define HDIM  128

// ---------------- scratch (no cudaMalloc allowed) ----------------
__device__ float g_q [S_LEN * EMB];
__device__ float g_k [S_LEN * EMB];
__device__ float g_v [S_LEN * EMB];
__device__ float g_ao[S_LEN * EMB];

// ---------------- GEMM: C[M,N] = A[M,K] * B[N,K]^T ----------------
// A, B, C row-major. BM=BN=128, BK=16, 256 threads, 8x8 per thread.
__global__ __launch_bounds__(256) void gemm_abt(
    const float* __restrict__ A, const float* __restrict__ B,
    float* __restrict__ C, int M, int N, int K)
{
    __shared__ __align__(16) float As[16][132];
    __shared__ __align__(16) float Bs[16][132];

    const int tid = threadIdx.x;
    const int tx = tid & 15;       // 0..15
    const int ty = tid >> 4;       // 0..15
    const int bm = blockIdx.y * 128;
    const int bn = blockIdx.x * 128;

    const int lrow = tid >> 2;            // 0..63
    const int lcol = (tid & 3) << 2;      // 0,4,8,12

    float acc[8][8];
#pragma unroll
    for (int i = 0; i < 8; i++)
#pragma unroll
        for (int j = 0; j < 8; j++) acc[i][j] = 0.f;

    for (int k0 = 0; k0 < K; k0 += 16) {
#pragma unroll
        for (int p = 0; p < 2; p++) {
            int r = lrow + p * 64;
            float4 va = *(const float4*)(A + (size_t)(bm + r) * K + k0 + lcol);
            As[lcol + 0][r] = va.x; As[lcol + 1][r] = va.y;
            As[lcol + 2][r] = va.z; As[lcol + 3][r] = va.w;
            float4 vb = *(const float4*)(B + (size_t)(bn + r) * K + k0 + lcol);
            Bs[lcol + 0][r] = vb.x; Bs[lcol + 1][r] = vb.y;
            Bs[lcol + 2][r] = vb.z; Bs[lcol + 3][r] = vb.w;
        }
        __syncthreads();
#pragma unroll
        for (int kk = 0; kk < 16; kk++) {
            float a[8], b[8];
            *(float4*)(a)     = *(const float4*)&As[kk][ty * 4];
            *(float4*)(a + 4) = *(const float4*)&As[kk][64 + ty * 4];
            *(float4*)(b)     = *(const float4*)&Bs[kk][tx * 4];
            *(float4*)(b + 4) = *(const float4*)&Bs[kk][64 + tx * 4];
#pragma unroll
            for (int i = 0; i < 8; i++)
#pragma unroll
                for (int j = 0; j < 8; j++)
                    acc[i][j] = fmaf(a[i], b[j], acc[i][j]);
        }
        __syncthreads();
    }

#pragma unroll
    for (int i = 0; i < 8; i++) {
        int row = bm + ((i < 4) ? (ty * 4 + i) : (64 + ty * 4 + (i - 4)));
        float4 v0 = make_float4(acc[i][0], acc[i][1], acc[i][2], acc[i][3]);
        float4 v1 = make_float4(acc[i][4], acc[i][5], acc[i][6], acc[i][7]);
        *(float4*)(C + (size_t)row * N + bn + tx * 4)      = v0;
        *(float4*)(C + (size_t)row * N + bn + 64 + tx * 4) = v1;
    }
}

// ---------------- RoPE (in-place on q and k; q also scaled 1/sqrt(d)) -----
__global__ __launch_bounds__(256) void rope_kernel(
    float* __restrict__ q, float* __restrict__ k,
    const float* __restrict__ cosb, const float* __restrict__ sinb)
{
    int idx = blockIdx.x * blockDim.x + threadIdx.x;
    const int total = S_LEN * NHEAD * (HDIM / 2);
    if (idx >= total) return;
    int d2 = idx & 63;
    int h  = (idx >> 6) & (NHEAD - 1);
    int s  = idx >> 10;

    float c1 = cosb[s * HDIM + d2];
    float s1 = sinb[s * HDIM + d2];
    float c2 = cosb[s * HDIM + 64 + d2];
    float s2 = sinb[s * HDIM + 64 + d2];

    const float scale = 0.088388347648318447f;  // 1/sqrt(128)
    size_t base = (size_t)s * EMB + h * HDIM;

    float q1 = q[base + d2], q2 = q[base + 64 + d2];
    q[base + d2]      = (q1 * c1 - q2 * s1) * scale;
    q[base + 64 + d2] = (q2 * c2 + q1 * s2) * scale;

    float k1 = k[base + d2], k2 = k[base + 64 + d2];
    k[base + d2]      = k1 * c1 - k2 * s1;
    k[base + 64 + d2] = k2 * c2 + k1 * s2;
}

// ---------------- Flash attention (causal, fp32) ----------------
// Grid: (32 q-blocks, 16 heads). Block: 256 threads. 64x64 tiles.
// smem: QsT[128][68], KsT[128][68], Vs[64][128], Ss[64][68], m/l/alpha[64]
#define FL_SMEM_FLOATS (2 * 128 * 68 + 64 * 128 + 64 * 68 + 3 * 64)
#define FL_SMEM_BYTES  (FL_SMEM_FLOATS * 4)

__global__ __launch_bounds__(256) void flash_attn(
    const float* __restrict__ q, const float* __restrict__ k,
    const float* __restrict__ v, float* __restrict__ o)
{
    const int ib = blockIdx.x;    // q block: rows ib*64 ..
    const int h  = blockIdx.y;

    extern __shared__ __align__(16) float sm[];
    float* Qs = sm;                   // [128][68]  Qs[d][r]
    float* Ks = Qs + 128 * 68;        // [128][68]  Ks[d][r]
    float* Vs = Ks + 128 * 68;        // [64][128]  row-major
    float* Ss = Vs + 64 * 128;        // [64][68]
    float* ms = Ss + 64 * 68;
    float* ls = ms + 64;
    float* al = ls + 64;

    const int tid  = threadIdx.x;
    const int lane = tid & 31;
    const int w    = tid >> 5;
    const int tx   = tid & 15;
    const int ty   = tid >> 4;

    // transposed-load lane mapping: lanes vary row within a warp (conflict-light STS)
    const int lr = (lane >> 2) + 8 * w;   // 0..63 (row within tile)
    const int lc = lane & 3;              // d-group base

    // ---- load Q (transposed) ----
    {
        const float* qrow = q + (size_t)(ib * 64 + lr) * EMB + h * HDIM;
#pragma unroll
        for (int it = 0; it < 8; it++) {
            int c4 = lc + 4 * it;
            float4 vq = *(const float4*)(qrow + c4 * 4);
            Qs[(c4 * 4 + 0) * 68 + lr] = vq.x;
            Qs[(c4 * 4 + 1) * 68 + lr] = vq.y;
            Qs[(c4 * 4 + 2) * 68 + lr] = vq.z;
            Qs[(c4 * 4 + 3) * 68 + lr] = vq.w;
        }
    }
    if (tid < 64) { ms[tid] = -1e30f; ls[tid] = 0.f; }

    float acc_o[4][8];
#pragma unroll
    for (int i = 0; i < 4; i++)
#pragma unroll
        for (int j = 0; j < 8; j++) acc_o[i][j] = 0.f;

    __syncthreads();

    for (int jb = 0; jb <= ib; jb++) {
        // ---- load K (transposed) + V (row-major) ----
        {
            const float* krow = k + (size_t)(jb * 64 + lr) * EMB + h * HDIM;
#pragma unroll
            for (int it = 0; it < 8; it++) {
                int c4 = lc + 4 * it;
                float4 vk = *(const float4*)(krow + c4 * 4);
                Ks[(c4 * 4 + 0) * 68 + lr] = vk.x;
                Ks[(c4 * 4 + 1) * 68 + lr] = vk.y;
                Ks[(c4 * 4 + 2) * 68 + lr] = vk.z;
                Ks[(c4 * 4 + 3) * 68 + lr] = vk.w;
            }
#pragma unroll
            for (int it = 0; it < 8; it++) {
                int i = tid + it * 256;
                int r = i >> 5, c4 = i & 31;
                *(float4*)(Vs + r * 128 + c4 * 4) =
                    *(const float4*)(v + (size_t)(jb * 64 + r) * EMB + h * HDIM + c4 * 4);
            }
        }
        __syncthreads();

        // ---- S = Q K^T  (4x4 per thread; rows ty*4.., cols tx*4..) ----
        float s[4][4];
#pragma unroll
        for (int i = 0; i < 4; i++)
#pragma unroll
            for (int j = 0; j < 4; j++) s[i][j] = 0.f;

#pragma unroll 4
        for (int kk = 0; kk < 128; kk++) {
            float a[4], b[4];
            *(float4*)a = *(const float4*)(Qs + kk * 68 + ty * 4);
            *(float4*)b = *(const float4*)(Ks + kk * 68 + tx * 4);
#pragma unroll
            for (int i = 0; i < 4; i++)
#pragma unroll
                for (int j = 0; j < 4; j++)
                    s[i][j] = fmaf(a[i], b[j], s[i][j]);
        }

        // causal mask within diagonal block, store to shared
        const bool diag = (jb == ib);
#pragma unroll
        for (int i = 0; i < 4; i++) {
            int row = ty * 4 + i;
#pragma unroll
            for (int j = 0; j < 4; j++) {
                int col = tx * 4 + j;
                if (diag && col > row) s[i][j] = -1e30f;
            }
            float4 sv = make_float4(s[i][0], s[i][1], s[i][2], s[i][3]);
            *(float4*)(Ss + row * 68 + tx * 4) = sv;
        }
        __syncthreads();

        // ---- online softmax bookkeeping (one thread per row) ----
        if (tid < 64) {
            float m_old = ms[tid];
            float mx = m_old;
#pragma unroll 8
            for (int j = 0; j < 64; j++) mx = fmaxf(mx, Ss[tid * 68 + j]);
            float alpha = __expf(m_old - mx);
            float sum = 0.f;
#pragma unroll 8
            for (int j = 0; j < 64; j++) {
                float p = __expf(Ss[tid * 68 + j] - mx);
                Ss[tid * 68 + j] = p;
                sum += p;
            }
            ms[tid] = mx;
            ls[tid] = ls[tid] * alpha + sum;
            al[tid] = alpha;
        }
        __syncthreads();

        // ---- O = O*alpha + P @ V ; rows ty*4.., cols tx*4.. and 64+tx*4.. ----
        float alpha_r[4];
#pragma unroll
        for (int i = 0; i < 4; i++) alpha_r[i] = al[ty * 4 + i];
#pragma unroll
        for (int i = 0; i < 4; i++)
#pragma unroll
            for (int j = 0; j < 8; j++) acc_o[i][j] *= alpha_r[i];

#pragma unroll 4
        for (int kk = 0; kk < 64; kk++) {
            float p[4], vv[8];
#pragma unroll
            for (int i = 0; i < 4; i++) p[i] = Ss[(ty * 4 + i) * 68 + kk];
            *(float4*)(vv)     = *(const float4*)(Vs + kk * 128 + tx * 4);
            *(float4*)(vv + 4) = *(const float4*)(Vs + kk * 128 + 64 + tx * 4);
#pragma unroll
            for (int i = 0; i < 4; i++)
#pragma unroll
                for (int j = 0; j < 8; j++)
                    acc_o[i][j] = fmaf(p[i], vv[j], acc_o[i][j]);
        }
        __syncthreads();   // protect Ks/Vs/Ss for next jb
    }

    // ---- epilogue: divide by l, write [s, e] layout ----
#pragma unroll
    for (int i = 0; i < 4; i++) {
        int row = ty * 4 + i;
        float inv = 1.f / ls[row];
        size_t gbase = (size_t)(ib * 64 + row) * EMB + h * HDIM;
        float4 o0 = make_float4(acc_o[i][0] * inv, acc_o[i][1] * inv,
                                acc_o[i][2] * inv, acc_o[i][3] * inv);
        float4 o1 = make_float4(acc_o[i][4] * inv, acc_o[i][5] * inv,
                                acc_o[i][6] * inv, acc_o[i][7] * inv);
        *(float4*)(o + gbase + tx * 4)      = o0;
        *(float4*)(o + gbase + 64 + tx * 4) = o1;
    }
}

// ---------------- launch ----------------
extern "C" void kernel_launch(void* const* d_in, const int* in_sizes, int n_in,
                              void* d_out, int out_size)
{
    const float* x  = (const float*)d_in[0];
    const float* rc = (const float*)d_in[1];
    const float* rs = (const float*)d_in[2];
    const float* Wq = (const float*)d_in[3];
    const float* Wk = (const float*)d_in[4];
    const float* Wv = (const float*)d_in[5];
    const float* Wo = (const float*)d_in[6];
    float* out = (float*)d_out;

    float *q, *k, *v, *ao;
    cudaGetSymbolAddress((void**)&q,  g_q);
    cudaGetSymbolAddress((void**)&k,  g_k);
    cudaGetSymbolAddress((void**)&v,  g_v);
    cudaGetSymbolAddress((void**)&ao, g_ao);

    cudaFuncSetAttribute(flash_attn,
                         cudaFuncAttributeMaxDynamicSharedMemorySize,
                         FL_SMEM_BYTES);

    dim3 gemm_grid(EMB / 128, S_LEN / 128);   // (16, 16)
    gemm_abt<<<gemm_grid, 256>>>(x, Wq, q, S_LEN, EMB, EMB);
    gemm_abt<<<gemm_grid, 256>>>(x, Wk, k, S_LEN, EMB, EMB);
    gemm_abt<<<gemm_grid, 256>>>(x, Wv, v, S_LEN, EMB, EMB);

    int rope_n = S_LEN * NHEAD * (HDIM / 2);
    rope_kernel<<<(rope_n + 255) / 256, 256>>>(q, k, rc, rs);

    flash_attn<<<dim3(S_LEN / 64, NHEAD), 256, FL_SMEM_BYTES>>>(q, k, v, ao);

    gemm_abt<<<gemm_grid, 256>>>(ao, Wo, out, S_LEN, EMB, EMB);
}